// round 17
// baseline (speedup 1.0000x reference)
#include <cuda_runtime.h>
#include <cuda_bf16.h>
#include <math.h>
#include <stdint.h>

#define NN 20000
#define TT 10
#define HH 64
#define EE 200000
#define NT (NN*TT)          // 200000 rows (NT % 64 == 0)
#define ROWF 640
#define BN_SCALE_C 0.99999500003749971893f

// ---------------- scratch ----------------
__device__ __align__(256) __nv_bfloat16 g_h0[NT*HH];   // projected features (bf16)
__device__ __align__(256) __nv_bfloat16 g_h1[NT*HH];
__device__ __align__(256) float g_s0[NT];
__device__ __align__(256) float g_s1[NT];
__device__ __align__(256) float g_X[NT*HH];
__device__ __align__(256) float g_c1[NT*64];
__device__ __align__(256) float g_c2[NT*32];
__device__ __align__(256) int   g_deg[2][NN];     // zero-init; self-restoring
__device__ __align__(256) int   g_rowptr[2][NN+1];
__device__ __align__(256) int   g_eord[2][EE];

// ---------------- CSR build ----------------
__global__ void k_count(const int* __restrict__ ei) {
    int idx = blockIdx.x*blockDim.x + threadIdx.x;
    if (idx >= 2*EE) return;
    int ty = idx / EE, e = idx % EE;
    int dst = ei[ty*2*EE + EE + e];
    atomicAdd(&g_deg[ty][dst], 1);
}

__global__ void k_scan() {
    int ty = blockIdx.x;
    __shared__ int wsums[32];
    int tid = threadIdx.x;
    int lane = tid & 31, w = tid >> 5;
    int start = tid * 20;
    int vals[20];
    int local = 0;
    #pragma unroll
    for (int j = 0; j < 20; j++) {
        int i = start + j;
        vals[j] = (i < NN) ? g_deg[ty][i] : 0;
        local += vals[j];
    }
    int pre = local;
    #pragma unroll
    for (int o = 1; o < 32; o <<= 1) {
        int v = __shfl_up_sync(0xFFFFFFFFu, pre, o);
        if (lane >= o) pre += v;
    }
    if (lane == 31) wsums[w] = pre;
    __syncthreads();
    if (w == 0) {
        int v = wsums[lane];
        int p = v;
        #pragma unroll
        for (int o = 1; o < 32; o <<= 1) {
            int t2 = __shfl_up_sync(0xFFFFFFFFu, p, o);
            if (lane >= o) p += t2;
        }
        wsums[lane] = p - v;
    }
    __syncthreads();
    int offset = wsums[w] + pre - local;
    #pragma unroll
    for (int j = 0; j < 20; j++) {
        int i = start + j;
        if (i < NN) g_rowptr[ty][i] = offset;
        offset += vals[j];
    }
    if (tid == 1023) g_rowptr[ty][NN] = offset;
}

__global__ void k_scatter(const int* __restrict__ ei) {
    int idx = blockIdx.x*blockDim.x + threadIdx.x;
    if (idx >= 2*EE) return;
    int ty = idx / EE, e = idx % EE;
    int dst = ei[ty*2*EE + EE + e];
    int pos = g_rowptr[ty][dst] + (atomicSub(&g_deg[ty][dst], 1) - 1);
    g_eord[ty][pos] = e;
}

// ---------------- helpers ----------------
__device__ __forceinline__ void split4(float4 v, __nv_bfloat16* hi, __nv_bfloat16* lo) {
    __nv_bfloat16 h0 = __float2bfloat16(v.x), h1 = __float2bfloat16(v.y);
    __nv_bfloat16 h2 = __float2bfloat16(v.z), h3 = __float2bfloat16(v.w);
    *(__nv_bfloat162*)(hi)     = __nv_bfloat162(h0, h1);
    *(__nv_bfloat162*)(hi + 2) = __nv_bfloat162(h2, h3);
    *(__nv_bfloat162*)(lo)     = __nv_bfloat162(
        __float2bfloat16(v.x - __bfloat162float(h0)),
        __float2bfloat16(v.y - __bfloat162float(h1)));
    *(__nv_bfloat162*)(lo + 2) = __nv_bfloat162(
        __float2bfloat16(v.z - __bfloat162float(h2)),
        __float2bfloat16(v.w - __bfloat162float(h3)));
}

// ---------------- tensor-core GEMM (bf16x3), ONE edge type -----------------
#define GEMM5_SMEM_BYTES 36864
__global__ void __launch_bounds__(128) k_gemm5(
    const float* __restrict__ Xin, int useX,
    const float* __restrict__ W, const float* __restrict__ bp,
    const float* __restrict__ ap, int idx4, int t)
{
    extern __shared__ __nv_bfloat16 smb[];
    __nv_bfloat16* Xh = smb;                 // [64][72]
    __nv_bfloat16* Xl = smb + 4608;
    __nv_bfloat16* Wh = smb + 9216;
    __nv_bfloat16* Wl = smb + 13824;

    const float* X = useX ? Xin : (const float*)g_X;
    int tid = threadIdx.x;
    int base = blockIdx.x * 64;

    {
        const float4* Xg = (const float4*)(X + (size_t)base*64);
        #pragma unroll
        for (int v = 0; v < 8; v++) {
            int idx = tid + v*128;
            float4 x4 = Xg[idx];
            int row = idx >> 4, c = (idx & 15)*4;
            split4(x4, Xh + row*72 + c, Xl + row*72 + c);
        }
    }
    {
        const float4* Wg = (const float4*)(W + (size_t)idx4*4096);
        #pragma unroll
        for (int v = 0; v < 8; v++) {
            int idx = tid + v*128;
            float4 w4 = Wg[idx];
            int row = idx >> 4, c = (idx & 15)*4;
            split4(w4, Wh + row*72 + c, Wl + row*72 + c);
        }
    }
    __syncthreads();

    int warp = tid >> 5, lane = tid & 31;
    int g = lane >> 2, tg = lane & 3;
    int m0 = warp*16;
    int a_row = m0 + (lane & 15);
    int a_col = (lane & 16) ? 8 : 0;
    uint32_t addrXh = (uint32_t)__cvta_generic_to_shared(Xh + a_row*72 + a_col);
    uint32_t addrXl = (uint32_t)__cvta_generic_to_shared(Xl + a_row*72 + a_col);
    int b_row = (lane & 15);

    float c[8][4];
    #pragma unroll
    for (int n = 0; n < 8; n++)
        #pragma unroll
        for (int i = 0; i < 4; i++) c[n][i] = 0.f;

    #pragma unroll
    for (int ks = 0; ks < 4; ks++) {
        uint32_t ah0, ah1, ah2, ah3, al0, al1, al2, al3;
        asm volatile("ldmatrix.sync.aligned.m8n8.x4.shared.b16 {%0,%1,%2,%3}, [%4];"
            : "=r"(ah0), "=r"(ah1), "=r"(ah2), "=r"(ah3) : "r"(addrXh + ks*32));
        asm volatile("ldmatrix.sync.aligned.m8n8.x4.shared.b16 {%0,%1,%2,%3}, [%4];"
            : "=r"(al0), "=r"(al1), "=r"(al2), "=r"(al3) : "r"(addrXl + ks*32));
        uint32_t wbh = (uint32_t)__cvta_generic_to_shared(Wh + (ks*16 + b_row)*72);
        uint32_t wbl = (uint32_t)__cvta_generic_to_shared(Wl + (ks*16 + b_row)*72);
        #pragma unroll
        for (int n = 0; n < 8; n++) {
            uint32_t bh0, bh1, bl0, bl1;
            asm volatile("ldmatrix.sync.aligned.m8n8.x2.trans.shared.b16 {%0,%1}, [%2];"
                : "=r"(bh0), "=r"(bh1) : "r"(wbh + n*16));
            asm volatile("ldmatrix.sync.aligned.m8n8.x2.trans.shared.b16 {%0,%1}, [%2];"
                : "=r"(bl0), "=r"(bl1) : "r"(wbl + n*16));
            asm volatile("mma.sync.aligned.m16n8k16.row.col.f32.bf16.bf16.f32 "
                "{%0,%1,%2,%3}, {%4,%5,%6,%7}, {%8,%9}, {%0,%1,%2,%3};"
                : "+f"(c[n][0]), "+f"(c[n][1]), "+f"(c[n][2]), "+f"(c[n][3])
                : "r"(ah0), "r"(ah1), "r"(ah2), "r"(ah3), "r"(bh0), "r"(bh1));
            asm volatile("mma.sync.aligned.m16n8k16.row.col.f32.bf16.bf16.f32 "
                "{%0,%1,%2,%3}, {%4,%5,%6,%7}, {%8,%9}, {%0,%1,%2,%3};"
                : "+f"(c[n][0]), "+f"(c[n][1]), "+f"(c[n][2]), "+f"(c[n][3])
                : "r"(ah0), "r"(ah1), "r"(ah2), "r"(ah3), "r"(bl0), "r"(bl1));
            asm volatile("mma.sync.aligned.m16n8k16.row.col.f32.bf16.bf16.f32 "
                "{%0,%1,%2,%3}, {%4,%5,%6,%7}, {%8,%9}, {%0,%1,%2,%3};"
                : "+f"(c[n][0]), "+f"(c[n][1]), "+f"(c[n][2]), "+f"(c[n][3])
                : "r"(al0), "r"(al1), "r"(al2), "r"(al3), "r"(bh0), "r"(bh1));
        }
    }

    const float* bP = bp + idx4*64;
    const float* aP = ap + idx4*64;
    __nv_bfloat16* hout = t ? (__nv_bfloat16*)g_h1 : (__nv_bfloat16*)g_h0;
    float* sout = t ? (float*)g_s1 : (float*)g_s0;
    int r0 = base + m0 + g, r1 = r0 + 8;
    float sd0 = 0.f, sd1 = 0.f;
    #pragma unroll
    for (int n = 0; n < 8; n++) {
        int col = n*8 + tg*2;
        float bb0 = bP[col], bb1 = bP[col+1];
        float h00 = c[n][0] + bb0, h01 = c[n][1] + bb1;
        float h10 = c[n][2] + bb0, h11 = c[n][3] + bb1;
        *(__nv_bfloat162*)(hout + (size_t)r0*64 + col) =
            __nv_bfloat162(__float2bfloat16(h00), __float2bfloat16(h01));
        *(__nv_bfloat162*)(hout + (size_t)r1*64 + col) =
            __nv_bfloat162(__float2bfloat16(h10), __float2bfloat16(h11));
        float a0 = aP[col], a1 = aP[col+1];
        sd0 += h00*a0 + h01*a1;
        sd1 += h10*a0 + h11*a1;
    }
    sd0 += __shfl_xor_sync(0xFFFFFFFFu, sd0, 1);
    sd0 += __shfl_xor_sync(0xFFFFFFFFu, sd0, 2);
    sd1 += __shfl_xor_sync(0xFFFFFFFFu, sd1, 1);
    sd1 += __shfl_xor_sync(0xFFFFFFFFu, sd1, 2);
    if (tg == 0) { sout[r0] = sd0; sout[r1] = sd1; }
}

// ---------------- warp-per-node attention (both types) + residual + LN -----
// One warp per destination node; 8 nodes per 256-thread block. No block
// barriers in the hot path. Lane owns h-pair (2*lane, 2*lane+1) for all t.
__global__ void __launch_bounds__(256) k_agg6(
    const float* __restrict__ xin, int useX,
    const int* __restrict__ ei, const float* __restrict__ ea,
    const float* __restrict__ lng, const float* __restrict__ lnb)
{
    const unsigned FULL = 0xFFFFFFFFu;
    int warp = threadIdx.x >> 5, lane = threadIdx.x & 31;
    int n = blockIdx.x*8 + warp;          // NN/8 = 2500 blocks exactly

    float acc[10][2];
    #pragma unroll
    for (int t = 0; t < 10; t++) { acc[t][0] = 0.f; acc[t][1] = 0.f; }

    #pragma unroll
    for (int ty = 0; ty < 2; ty++) {
        const float* sA   = ty ? (const float*)g_s1 : (const float*)g_s0;
        const __nv_bfloat16* hA = ty ? (const __nv_bfloat16*)g_h1
                                     : (const __nv_bfloat16*)g_h0;
        const float* eaA  = ea + ty*EE;
        const int*   srcA = ei + ty*2*EE;
        const int*   eord = g_eord[ty];
        int r0 = g_rowptr[ty][n], r1 = g_rowptr[ty][n+1];

        float m[10], dsum[10];
        #pragma unroll
        for (int t = 0; t < 10; t++) { m[t] = -1e30f; dsum[t] = 0.f; }

        // pass 1: online softmax stats, 32 edges per chunk, lane = edge
        for (int j0 = r0; j0 < r1; j0 += 32) {
            int cnt = min(32, r1 - j0);
            int act = lane < cnt;
            int e   = act ? eord[j0 + lane] : 0;
            int src = act ? srcA[e] : 0;
            const float* sp = sA + src*TT;
            float sv[10];
            #pragma unroll
            for (int t = 0; t < 10; t++) {
                float v = sp[t];
                sv[t] = v > 0.f ? v : 0.2f*v;
            }
            #pragma unroll
            for (int t = 0; t < 10; t++) {
                float cm = act ? sv[t] : -1e30f;
                #pragma unroll
                for (int o = 16; o >= 1; o >>= 1)
                    cm = fmaxf(cm, __shfl_xor_sync(FULL, cm, o));
                float nm = fmaxf(m[t], cm);
                float el = act ? __expf(sv[t] - nm) : 0.f;
                #pragma unroll
                for (int o = 16; o >= 1; o >>= 1)
                    el += __shfl_xor_sync(FULL, el, o);
                dsum[t] = dsum[t]*__expf(m[t] - nm) + el;
                m[t] = nm;
            }
        }
        float rcp[10];
        #pragma unroll
        for (int t = 0; t < 10; t++) rcp[t] = 1.f/(dsum[t] + 1e-16f);

        // pass 2: weights in lane registers, gather with per-edge shfl bcast
        for (int j0 = r0; j0 < r1; j0 += 32) {
            int cnt = min(32, r1 - j0);
            int act = lane < cnt;
            int e   = act ? eord[j0 + lane] : 0;
            int src = act ? srcA[e] : 0;
            float eav = act ? eaA[e] : 0.f;
            const float* sp = sA + src*TT;
            float wt[10];
            #pragma unroll
            for (int t = 0; t < 10; t++) {
                float v = sp[t];
                float sc = v > 0.f ? v : 0.2f*v;
                wt[t] = __expf(sc - m[t]) * rcp[t] * eav;
            }
            for (int c = 0; c < cnt; c++) {
                int sb = __shfl_sync(FULL, src, c);
                const __nv_bfloat16* hr = hA + (size_t)sb*ROWF + 2*lane;
                #pragma unroll
                for (int t = 0; t < 10; t++) {
                    float w = __shfl_sync(FULL, wt[t], c);
                    __nv_bfloat162 hv = *(const __nv_bfloat162*)(hr + t*64);
                    float2 f = __bfloat1622float2(hv);
                    acc[t][0] += w*f.x;
                    acc[t][1] += w*f.y;
                }
            }
        }
    }

    // residual + LayerNorm (per-t warp reductions)
    const float* Xsrc = (useX ? xin : (const float*)g_X) + (size_t)n*ROWF + 2*lane;
    float* Xo = g_X + (size_t)n*ROWF + 2*lane;
    float gw0 = lng[2*lane], gw1 = lng[2*lane + 1];
    float bw0 = lnb[2*lane], bw1 = lnb[2*lane + 1];
    #pragma unroll
    for (int t = 0; t < 10; t++) {
        float2 xv = *(const float2*)(Xsrc + t*64);
        float v0 = xv.x + 0.5f*acc[t][0];
        float v1 = xv.y + 0.5f*acc[t][1];
        float s = v0 + v1, q = v0*v0 + v1*v1;
        #pragma unroll
        for (int o = 16; o >= 1; o >>= 1) {
            s += __shfl_xor_sync(FULL, s, o);
            q += __shfl_xor_sync(FULL, q, o);
        }
        float mean = s * (1.f/64.f);
        float var  = q * (1.f/64.f) - mean*mean;
        float inv  = rsqrtf(var + 1e-5f);
        float2 o2;
        o2.x = (v0 - mean)*inv*gw0 + bw0;
        o2.y = (v1 - mean)*inv*gw1 + bw1;
        *(float2*)(Xo + t*64) = o2;
    }
}

// ---------------- tensorized decoder conv1 (64->64, k=3) --------------------
#define CONV_SMEM_BYTES 110592
#define CONV_GRID 296
__global__ void __launch_bounds__(128) k_conv1(
    const float* __restrict__ cw1, const float* __restrict__ cb1,
    const float* __restrict__ bn1g, const float* __restrict__ bn1b)
{
    extern __shared__ __nv_bfloat16 smc[];
    __nv_bfloat16* A  = smc;            // [shift][hi/lo][64*72]
    __nv_bfloat16* Wk = smc + 27648;
    int tid = threadIdx.x;

    for (int idx = tid; idx < 4096; idx += 128) {
        int i = idx >> 6, o = idx & 63;
        #pragma unroll
        for (int k = 0; k < 3; k++) {
            float w = cw1[o*192 + i*3 + k];
            __nv_bfloat16 h = __float2bfloat16(w);
            Wk[(k*2+0)*4608 + i*72 + o] = h;
            Wk[(k*2+1)*4608 + i*72 + o] = __float2bfloat16(w - __bfloat162float(h));
        }
    }
    __syncthreads();

    int warp = tid >> 5, lane = tid & 31;
    int g = lane >> 2, tg = lane & 3;
    int m0 = warp*16;
    int a_row = m0 + (lane & 15);
    int a_col = (lane & 16) ? 8 : 0;
    int b_row = (lane & 15);

    for (int tile = blockIdx.x; tile < NT/64; tile += CONV_GRID) {
        int base = tile*64;
        for (int idx = tid; idx < 1024; idx += 128) {
            int row = idx >> 4, c4 = (idx & 15)*4;
            int t = (base + row) % 10;
            #pragma unroll
            for (int s = 0; s < 3; s++) {
                int dt = s - 1;
                float4 x4 = make_float4(0.f,0.f,0.f,0.f);
                if ((unsigned)(t + dt) < 10u)
                    x4 = *(const float4*)(g_X + (size_t)(base + row + dt)*64 + c4);
                split4(x4, A + (s*2+0)*4608 + row*72 + c4,
                           A + (s*2+1)*4608 + row*72 + c4);
            }
        }
        __syncthreads();

        float c[8][4];
        #pragma unroll
        for (int n = 0; n < 8; n++)
            #pragma unroll
            for (int i = 0; i < 4; i++) c[n][i] = 0.f;

        #pragma unroll
        for (int s = 0; s < 3; s++) {
            uint32_t aH = (uint32_t)__cvta_generic_to_shared(
                A + (s*2+0)*4608 + a_row*72 + a_col);
            uint32_t aL = (uint32_t)__cvta_generic_to_shared(
                A + (s*2+1)*4608 + a_row*72 + a_col);
            #pragma unroll
            for (int ks = 0; ks < 4; ks++) {
                uint32_t ah0, ah1, ah2, ah3, al0, al1, al2, al3;
                asm volatile("ldmatrix.sync.aligned.m8n8.x4.shared.b16 {%0,%1,%2,%3}, [%4];"
                    : "=r"(ah0), "=r"(ah1), "=r"(ah2), "=r"(ah3) : "r"(aH + ks*32));
                asm volatile("ldmatrix.sync.aligned.m8n8.x4.shared.b16 {%0,%1,%2,%3}, [%4];"
                    : "=r"(al0), "=r"(al1), "=r"(al2), "=r"(al3) : "r"(aL + ks*32));
                uint32_t wbh = (uint32_t)__cvta_generic_to_shared(
                    Wk + (s*2+0)*4608 + (ks*16 + b_row)*72);
                uint32_t wbl = (uint32_t)__cvta_generic_to_shared(
                    Wk + (s*2+1)*4608 + (ks*16 + b_row)*72);
                #pragma unroll
                for (int n = 0; n < 8; n++) {
                    uint32_t bh0, bh1, bl0, bl1;
                    asm volatile("ldmatrix.sync.aligned.m8n8.x2.trans.shared.b16 {%0,%1}, [%2];"
                        : "=r"(bh0), "=r"(bh1) : "r"(wbh + n*16));
                    asm volatile("ldmatrix.sync.aligned.m8n8.x2.trans.shared.b16 {%0,%1}, [%2];"
                        : "=r"(bl0), "=r"(bl1) : "r"(wbl + n*16));
                    asm volatile("mma.sync.aligned.m16n8k16.row.col.f32.bf16.bf16.f32 "
                        "{%0,%1,%2,%3}, {%4,%5,%6,%7}, {%8,%9}, {%0,%1,%2,%3};"
                        : "+f"(c[n][0]), "+f"(c[n][1]), "+f"(c[n][2]), "+f"(c[n][3])
                        : "r"(ah0), "r"(ah1), "r"(ah2), "r"(ah3), "r"(bh0), "r"(bh1));
                    asm volatile("mma.sync.aligned.m16n8k16.row.col.f32.bf16.bf16.f32 "
                        "{%0,%1,%2,%3}, {%4,%5,%6,%7}, {%8,%9}, {%0,%1,%2,%3};"
                        : "+f"(c[n][0]), "+f"(c[n][1]), "+f"(c[n][2]), "+f"(c[n][3])
                        : "r"(ah0), "r"(ah1), "r"(ah2), "r"(ah3), "r"(bl0), "r"(bl1));
                    asm volatile("mma.sync.aligned.m16n8k16.row.col.f32.bf16.bf16.f32 "
                        "{%0,%1,%2,%3}, {%4,%5,%6,%7}, {%8,%9}, {%0,%1,%2,%3};"
                        : "+f"(c[n][0]), "+f"(c[n][1]), "+f"(c[n][2]), "+f"(c[n][3])
                        : "r"(al0), "r"(al1), "r"(al2), "r"(al3), "r"(bh0), "r"(bh1));
                }
            }
        }

        int r0 = base + m0 + g, r1 = r0 + 8;
        #pragma unroll
        for (int n = 0; n < 8; n++) {
            int col = n*8 + tg*2;
            float cb0 = cb1[col], cb1v = cb1[col+1];
            float s0 = bn1g[col]*BN_SCALE_C,  t0 = bn1b[col];
            float s1 = bn1g[col+1]*BN_SCALE_C, t1 = bn1b[col+1];
            float y00 = (c[n][0]+cb0)*s0 + t0; y00 = y00 > 0.f ? y00 : 0.f;
            float y01 = (c[n][1]+cb1v)*s1 + t1; y01 = y01 > 0.f ? y01 : 0.f;
            float y10 = (c[n][2]+cb0)*s0 + t0; y10 = y10 > 0.f ? y10 : 0.f;
            float y11 = (c[n][3]+cb1v)*s1 + t1; y11 = y11 > 0.f ? y11 : 0.f;
            *(float2*)(g_c1 + (size_t)r0*64 + col) = make_float2(y00, y01);
            *(float2*)(g_c1 + (size_t)r1*64 + col) = make_float2(y10, y11);
        }
        __syncthreads();
    }
}

// ---------------- tensorized decoder conv2 (64->32, k=3) --------------------
__global__ void __launch_bounds__(128) k_conv2(
    const float* __restrict__ cw2, const float* __restrict__ cb2,
    const float* __restrict__ bn2g, const float* __restrict__ bn2b)
{
    extern __shared__ __nv_bfloat16 smc[];
    __nv_bfloat16* A  = smc;
    __nv_bfloat16* Wk = smc + 27648;
    int tid = threadIdx.x;

    for (int idx = tid; idx < 2048; idx += 128) {
        int i = idx >> 5, o = idx & 31;
        #pragma unroll
        for (int k = 0; k < 3; k++) {
            float w = cw2[o*192 + i*3 + k];
            __nv_bfloat16 h = __float2bfloat16(w);
            Wk[(k*2+0)*4608 + i*72 + o] = h;
            Wk[(k*2+1)*4608 + i*72 + o] = __float2bfloat16(w - __bfloat162float(h));
        }
    }
    __syncthreads();

    int warp = tid >> 5, lane = tid & 31;
    int g = lane >> 2, tg = lane & 3;
    int m0 = warp*16;
    int a_row = m0 + (lane & 15);
    int a_col = (lane & 16) ? 8 : 0;
    int b_row = (lane & 15);

    for (int tile = blockIdx.x; tile < NT/64; tile += CONV_GRID) {
        int base = tile*64;
        for (int idx = tid; idx < 1024; idx += 128) {
            int row = idx >> 4, c4 = (idx & 15)*4;
            int t = (base + row) % 10;
            #pragma unroll
            for (int s = 0; s < 3; s++) {
                int dt = s - 1;
                float4 x4 = make_float4(0.f,0.f,0.f,0.f);
                if ((unsigned)(t + dt) < 10u)
                    x4 = *(const float4*)(g_c1 + (size_t)(base + row + dt)*64 + c4);
                split4(x4, A + (s*2+0)*4608 + row*72 + c4,
                           A + (s*2+1)*4608 + row*72 + c4);
            }
        }
        __syncthreads();

        float c[4][4];
        #pragma unroll
        for (int n = 0; n < 4; n++)
            #pragma unroll
            for (int i = 0; i < 4; i++) c[n][i] = 0.f;

        #pragma unroll
        for (int s = 0; s < 3; s++) {
            uint32_t aH = (uint32_t)__cvta_generic_to_shared(
                A + (s*2+0)*4608 + a_row*72 + a_col);
            uint32_t aL = (uint32_t)__cvta_generic_to_shared(
                A + (s*2+1)*4608 + a_row*72 + a_col);
            #pragma unroll
            for (int ks = 0; ks < 4; ks++) {
                uint32_t ah0, ah1, ah2, ah3, al0, al1, al2, al3;
                asm volatile("ldmatrix.sync.aligned.m8n8.x4.shared.b16 {%0,%1,%2,%3}, [%4];"
                    : "=r"(ah0), "=r"(ah1), "=r"(ah2), "=r"(ah3) : "r"(aH + ks*32));
                asm volatile("ldmatrix.sync.aligned.m8n8.x4.shared.b16 {%0,%1,%2,%3}, [%4];"
                    : "=r"(al0), "=r"(al1), "=r"(al2), "=r"(al3) : "r"(aL + ks*32));
                uint32_t wbh = (uint32_t)__cvta_generic_to_shared(
                    Wk + (s*2+0)*4608 + (ks*16 + b_row)*72);
                uint32_t wbl = (uint32_t)__cvta_generic_to_shared(
                    Wk + (s*2+1)*4608 + (ks*16 + b_row)*72);
                #pragma unroll
                for (int n = 0; n < 4; n++) {
                    uint32_t bh0, bh1, bl0, bl1;
                    asm volatile("ldmatrix.sync.aligned.m8n8.x2.trans.shared.b16 {%0,%1}, [%2];"
                        : "=r"(bh0), "=r"(bh1) : "r"(wbh + n*16));
                    asm volatile("ldmatrix.sync.aligned.m8n8.x2.trans.shared.b16 {%0,%1}, [%2];"
                        : "=r"(bl0), "=r"(bl1) : "r"(wbl + n*16));
                    asm volatile("mma.sync.aligned.m16n8k16.row.col.f32.bf16.bf16.f32 "
                        "{%0,%1,%2,%3}, {%4,%5,%6,%7}, {%8,%9}, {%0,%1,%2,%3};"
                        : "+f"(c[n][0]), "+f"(c[n][1]), "+f"(c[n][2]), "+f"(c[n][3])
                        : "r"(ah0), "r"(ah1), "r"(ah2), "r"(ah3), "r"(bh0), "r"(bh1));
                    asm volatile("mma.sync.aligned.m16n8k16.row.col.f32.bf16.bf16.f32 "
                        "{%0,%1,%2,%3}, {%4,%5,%6,%7}, {%8,%9}, {%0,%1,%2,%3};"
                        : "+f"(c[n][0]), "+f"(c[n][1]), "+f"(c[n][2]), "+f"(c[n][3])
                        : "r"(ah0), "r"(ah1), "r"(ah2), "r"(ah3), "r"(bl0), "r"(bl1));
                    asm volatile("mma.sync.aligned.m16n8k16.row.col.f32.bf16.bf16.f32 "
                        "{%0,%1,%2,%3}, {%4,%5,%6,%7}, {%8,%9}, {%0,%1,%2,%3};"
                        : "+f"(c[n][0]), "+f"(c[n][1]), "+f"(c[n][2]), "+f"(c[n][3])
                        : "r"(al0), "r"(al1), "r"(al2), "r"(al3), "r"(bh0), "r"(bh1));
                }
            }
        }

        int r0 = base + m0 + g, r1 = r0 + 8;
        #pragma unroll
        for (int n = 0; n < 4; n++) {
            int col = n*8 + tg*2;
            float cb0 = cb2[col], cb1v = cb2[col+1];
            float s0 = bn2g[col]*BN_SCALE_C,  t0 = bn2b[col];
            float s1 = bn2g[col+1]*BN_SCALE_C, t1 = bn2b[col+1];
            float y00 = (c[n][0]+cb0)*s0 + t0; y00 = y00 > 0.f ? y00 : 0.f;
            float y01 = (c[n][1]+cb1v)*s1 + t1; y01 = y01 > 0.f ? y01 : 0.f;
            float y10 = (c[n][2]+cb0)*s0 + t0; y10 = y10 > 0.f ? y10 : 0.f;
            float y11 = (c[n][3]+cb1v)*s1 + t1; y11 = y11 > 0.f ? y11 : 0.f;
            *(float2*)(g_c2 + (size_t)r0*32 + col) = make_float2(y00, y01);
            *(float2*)(g_c2 + (size_t)r1*32 + col) = make_float2(y10, y11);
        }
        __syncthreads();
    }
}

// ---------------- decoder conv3 (32->1, k=3): warp per output row ----------
__global__ void __launch_bounds__(256) k_conv3(
    const float* __restrict__ cw3, const float* __restrict__ cb3,
    float* __restrict__ out)
{
    int gw = (blockIdx.x*blockDim.x + threadIdx.x) >> 5;
    int lane = threadIdx.x & 31;
    if (gw >= NT) return;
    int t = gw % 10;
    float cm = (t > 0) ? g_c2[(size_t)(gw-1)*32 + lane] : 0.f;
    float c0 = g_c2[(size_t)gw*32 + lane];
    float cp = (t < 9) ? g_c2[(size_t)(gw+1)*32 + lane] : 0.f;
    float acc = cw3[lane*3+0]*cm + cw3[lane*3+1]*c0 + cw3[lane*3+2]*cp;
    #pragma unroll
    for (int m = 16; m >= 1; m >>= 1)
        acc += __shfl_xor_sync(0xFFFFFFFFu, acc, m);
    if (lane == 0) out[gw] = acc + cb3[0];
}

// ---------------- launch ----------------------------------------------------
extern "C" void kernel_launch(void* const* d_in, const int* in_sizes, int n_in,
                              void* d_out, int out_size)
{
    const float* x    = (const float*)d_in[0];
    const int*   ei   = (const int*)  d_in[1];
    const float* ea   = (const float*)d_in[2];
    const float* W    = (const float*)d_in[3];
    const float* bp   = (const float*)d_in[4];
    const float* ap   = (const float*)d_in[5];
    const float* lng  = (const float*)d_in[6];
    const float* lnb  = (const float*)d_in[7];
    const float* cw1  = (const float*)d_in[8];
    const float* cb1  = (const float*)d_in[9];
    const float* bn1g = (const float*)d_in[10];
    const float* bn1b = (const float*)d_in[11];
    const float* cw2  = (const float*)d_in[12];
    const float* cb2  = (const float*)d_in[13];
    const float* bn2g = (const float*)d_in[14];
    const float* bn2b = (const float*)d_in[15];
    const float* cw3  = (const float*)d_in[16];
    const float* cb3  = (const float*)d_in[17];
    float* out = (float*)d_out;

    static int attr_set = 0;
    if (!attr_set) {
        cudaFuncSetAttribute(k_gemm5, cudaFuncAttributeMaxDynamicSharedMemorySize,
                             GEMM5_SMEM_BYTES);
        cudaFuncSetAttribute(k_conv1, cudaFuncAttributeMaxDynamicSharedMemorySize,
                             CONV_SMEM_BYTES);
        cudaFuncSetAttribute(k_conv2, cudaFuncAttributeMaxDynamicSharedMemorySize,
                             CONV_SMEM_BYTES);
        attr_set = 1;
    }

    k_count<<<(2*EE + 255)/256, 256>>>(ei);
    k_scan<<<2, 1024>>>();
    k_scatter<<<(2*EE + 255)/256, 256>>>(ei);

    int gemm_grid = NT/64;
    for (int l = 0; l < 2; l++) {
        int useX = (l == 0) ? 1 : 0;
        k_gemm5<<<gemm_grid, 128, GEMM5_SMEM_BYTES>>>(x, useX, W, bp, ap, l*2+0, 0);
        k_gemm5<<<gemm_grid, 128, GEMM5_SMEM_BYTES>>>(x, useX, W, bp, ap, l*2+1, 1);
        k_agg6<<<NN/8, 256>>>(x, useX, ei, ea, lng + l*64, lnb + l*64);
    }

    k_conv1<<<CONV_GRID, 128, CONV_SMEM_BYTES>>>(cw1, cb1, bn1g, bn1b);
    k_conv2<<<CONV_GRID, 128, CONV_SMEM_BYTES>>>(cw2, cb2, bn2g, bn2b);
    k_conv3<<<NT/8, 256>>>(cw3, cb3, out);
}